// round 4
// baseline (speedup 1.0000x reference)
#include <cuda_runtime.h>
#include <math.h>

#define B_ROWS 8192
#define N_IN   12288
#define H0     256
#define H1     32
#define H2     32
#define CAP    192   // ~31 expected actives, std ~5.5; 192 is >25 sigma

// Transposed feature weights: wT[j][h] = ft_w[h][j]; 12288*256 fp32 = 12.6 MB (L2-resident)
__device__ float g_wT[N_IN * H0];

// ---------------------------------------------------------------------------
// Kernel 1: tiled transpose ft_w (256 x 12288) -> g_wT (12288 x 256)
// ---------------------------------------------------------------------------
__global__ void transpose_ftw(const float* __restrict__ ft_w) {
    __shared__ float tile[32][33];
    int jBase = blockIdx.x * 32;   // along N_IN
    int hBase = blockIdx.y * 32;   // along H0
    int tx = threadIdx.x, ty = threadIdx.y;   // (32, 8)
    #pragma unroll
    for (int r = ty; r < 32; r += 8)
        tile[r][tx] = ft_w[(size_t)(hBase + r) * N_IN + (jBase + tx)];
    __syncthreads();
    #pragma unroll
    for (int r = ty; r < 32; r += 8)
        g_wT[(size_t)(jBase + r) * H0 + (hBase + tx)] = tile[tx][r];
}

// ---------------------------------------------------------------------------
// Kernel 2: persistent NNUE forward. One thread per FT output unit (256/CTA).
// Dynamic smem: l1_w cache (32 x 512 fp32 = 64 KB).
// ---------------------------------------------------------------------------
extern __shared__ float s_l1w[];

__global__ void __launch_bounds__(256, 3)
nnue_main(const float4* __restrict__ wfeat,
          const float4* __restrict__ bfeat,
          const unsigned int* __restrict__ side,   // int32 or fp32 bool: nonzero word == true
          const float* __restrict__ ft_b,
          const float* __restrict__ l1_w,
          const float* __restrict__ l1_b,
          const float* __restrict__ l2_w,
          const float* __restrict__ l2_b,
          const float* __restrict__ l3_w,
          const float* __restrict__ l3_b,
          float* __restrict__ out)
{
    __shared__ float s_l2w[H2 * 33];     // stride-33 pad: conflict-free lane*33+i
    __shared__ float s_o0[2 * H0];
    __shared__ float s_o1[H1];
    __shared__ int   s_idxW[CAP], s_idxB[CAP];
    __shared__ int   s_cntW, s_cntB;

    const int tid  = threadIdx.x;
    const int warp = tid >> 5;
    const int lane = tid & 31;

    // One-time per-CTA: cache l1_w / l2_w in shared
    for (int i = tid; i < H1 * 2 * H0; i += 256) s_l1w[i] = l1_w[i];
    for (int i = tid; i < H2 * H1; i += 256)     s_l2w[(i >> 5) * 33 + (i & 31)] = l2_w[i];
    const float my_bias = ft_b[tid];

    for (int row = blockIdx.x; row < B_ROWS; row += gridDim.x) {
        if (tid == 0) { s_cntW = 0; s_cntB = 0; }
        __syncthreads();   // also covers first-iteration l1w visibility

        // ---- Phase 1: scan both feature rows (streaming), build active lists
        const float4* wrow = wfeat + (size_t)row * (N_IN / 4);
        const float4* brow = bfeat + (size_t)row * (N_IN / 4);
        for (int i = tid; i < N_IN / 4; i += 256) {
            float4 v = __ldcs(wrow + i);
            if (v.x != 0.f || v.y != 0.f || v.z != 0.f || v.w != 0.f) {
                if (v.x != 0.f) { int p = atomicAdd(&s_cntW, 1); if (p < CAP) s_idxW[p] = (4*i + 0) << 8; }
                if (v.y != 0.f) { int p = atomicAdd(&s_cntW, 1); if (p < CAP) s_idxW[p] = (4*i + 1) << 8; }
                if (v.z != 0.f) { int p = atomicAdd(&s_cntW, 1); if (p < CAP) s_idxW[p] = (4*i + 2) << 8; }
                if (v.w != 0.f) { int p = atomicAdd(&s_cntW, 1); if (p < CAP) s_idxW[p] = (4*i + 3) << 8; }
            }
            float4 u = __ldcs(brow + i);
            if (u.x != 0.f || u.y != 0.f || u.z != 0.f || u.w != 0.f) {
                if (u.x != 0.f) { int p = atomicAdd(&s_cntB, 1); if (p < CAP) s_idxB[p] = (4*i + 0) << 8; }
                if (u.y != 0.f) { int p = atomicAdd(&s_cntB, 1); if (p < CAP) s_idxB[p] = (4*i + 1) << 8; }
                if (u.z != 0.f) { int p = atomicAdd(&s_cntB, 1); if (p < CAP) s_idxB[p] = (4*i + 2) << 8; }
                if (u.w != 0.f) { int p = atomicAdd(&s_cntB, 1); if (p < CAP) s_idxB[p] = (4*i + 3) << 8; }
            }
        }
        __syncthreads();

        // ---- Phase 2: sparse FT accumulation (coalesced 1KB gathers from L2)
        const int nW = min(s_cntW, CAP);
        const int nB = min(s_cntB, CAP);
        float aW0 = my_bias, aW1 = 0.f, aB0 = my_bias, aB1 = 0.f;
        int k = 0;
        for (; k + 1 < nW; k += 2) {
            aW0 += __ldcs(&g_wT[s_idxW[k]     + tid]);
            aW1 += __ldcs(&g_wT[s_idxW[k + 1] + tid]);
        }
        if (k < nW) aW0 += __ldcs(&g_wT[s_idxW[k] + tid]);
        k = 0;
        for (; k + 1 < nB; k += 2) {
            aB0 += __ldcs(&g_wT[s_idxB[k]     + tid]);
            aB1 += __ldcs(&g_wT[s_idxB[k + 1] + tid]);
        }
        if (k < nB) aB0 += __ldcs(&g_wT[s_idxB[k] + tid]);

        const float o0w = fminf(fmaxf(aW0 + aW1, 0.f), 1.f);
        const float o0b = fminf(fmaxf(aB0 + aB1, 0.f), 1.f);

        const bool sd = (side[row] != 0u);    // works for int32 (1) and fp32 (0x3F800000)
        s_o0[tid]      = sd ? o0w : o0b;
        s_o0[H0 + tid] = sd ? o0b : o0w;
        __syncthreads();

        // ---- Phase 3: l1 = clip(o0 @ l1_w.T + b); 8 warps x 4 outputs
        for (int kk = warp; kk < H1; kk += 8) {
            const float* wp = &s_l1w[kk * 2 * H0];
            float s = 0.f;
            #pragma unroll
            for (int i = lane; i < 2 * H0; i += 32) s += s_o0[i] * wp[i];
            #pragma unroll
            for (int off = 16; off; off >>= 1) s += __shfl_xor_sync(0xffffffffu, s, off);
            if (lane == 0) s_o1[kk] = fminf(fmaxf(s + l1_b[kk], 0.f), 1.f);
        }
        __syncthreads();

        // ---- Phase 4: l2 + l3 + sigmoid, warp 0 (lane = l2 output unit)
        if (warp == 0) {
            float s = l2_b[lane];
            #pragma unroll
            for (int i = 0; i < H1; i++) s += s_o1[i] * s_l2w[lane * 33 + i];
            const float o2 = fminf(fmaxf(s, 0.f), 1.f);
            float p = o2 * l3_w[lane];
            #pragma unroll
            for (int off = 16; off; off >>= 1) p += __shfl_xor_sync(0xffffffffu, p, off);
            if (lane == 0) {
                // o3 = (dot + l3_b) * 300; out = sigmoid(o3 / 200) = sigmoid(1.5 * raw)
                const float o3 = (p + l3_b[0]) * 1.5f;
                out[row] = 1.f / (1.f + expf(-o3));
            }
        }
        __syncthreads();   // protect s_o0 / s_idx / counters before next row
    }
}

// ---------------------------------------------------------------------------
extern "C" void kernel_launch(void* const* d_in, const int* in_sizes, int n_in,
                              void* d_out, int out_size) {
    const float*        wfeat = (const float*)d_in[0];
    const float*        bfeat = (const float*)d_in[1];
    const unsigned int* side  = (const unsigned int*)d_in[2];
    const float*        ft_w  = (const float*)d_in[3];
    const float*        ft_b  = (const float*)d_in[4];
    const float*        l1_w  = (const float*)d_in[5];
    const float*        l1_b  = (const float*)d_in[6];
    const float*        l2_w  = (const float*)d_in[7];
    const float*        l2_b  = (const float*)d_in[8];
    const float*        l3_w  = (const float*)d_in[9];
    const float*        l3_b  = (const float*)d_in[10];
    float* out = (float*)d_out;

    // Kernel 1: transpose ft_w into g_wT (runs every launch; deterministic, ~4us)
    dim3 tb(32, 8);
    dim3 tg(N_IN / 32, H0 / 32);
    transpose_ftw<<<tg, tb>>>(ft_w);

    // Kernel 2: persistent main kernel, 64KB dynamic smem for the l1_w cache
    const int dyn_smem = H1 * 2 * H0 * (int)sizeof(float);   // 65536
    cudaFuncSetAttribute(nnue_main, cudaFuncAttributeMaxDynamicSharedMemorySize, dyn_smem);
    nnue_main<<<444, 256, dyn_smem>>>(
        (const float4*)wfeat, (const float4*)bfeat, side,
        ft_b, l1_w, l1_b, l2_w, l2_b, l3_w, l3_b, out);
}

// round 5
// speedup vs baseline: 1.7328x; 1.7328x over previous
#include <cuda_runtime.h>
#include <math.h>

#define B_ROWS 8192
#define N_IN   12288
#define H0     256
#define H1     32
#define H2     32
#define CAP    192          // ~31 expected actives/row; 192 is >25 sigma
#define MASK_WORDS 384      // 12288 bits / 32

// Transposed feature weights: wT[j][h] = ft_w[h][j]; 12.6 MB, L2-resident
__device__ float g_wT[N_IN * H0];
// Active-feature bitmasks: 3 KB per row per color, 25 MB total, L2-resident
__device__ unsigned g_maskW[B_ROWS * MASK_WORDS];
__device__ unsigned g_maskB[B_ROWS * MASK_WORDS];

// ---------------------------------------------------------------------------
// Kernel 1: tiled transpose ft_w (256 x 12288) -> g_wT (12288 x 256)
// ---------------------------------------------------------------------------
__global__ void transpose_ftw(const float* __restrict__ ft_w) {
    __shared__ float tile[32][33];
    int jBase = blockIdx.x * 32;
    int hBase = blockIdx.y * 32;
    int tx = threadIdx.x, ty = threadIdx.y;   // (32, 8)
    #pragma unroll
    for (int r = ty; r < 32; r += 8)
        tile[r][tx] = ft_w[(size_t)(hBase + r) * N_IN + (jBase + tx)];
    __syncthreads();
    #pragma unroll
    for (int r = ty; r < 32; r += 8)
        g_wT[(size_t)(jBase + r) * H0 + (hBase + tx)] = tile[tx][r];
}

// ---------------------------------------------------------------------------
// Kernel 2: streaming bitmask build. One warp-iteration = 128 consecutive
// floats (512B coalesced read) -> 4 ballot words (16B store by lane 0).
// Word layout: word (c*4+w), bit b  <=>  feature j = c*128 + 4*b + w.
// gridDim.y selects white(0)/black(1).
// ---------------------------------------------------------------------------
__global__ void __launch_bounds__(256)
build_masks(const float4* __restrict__ wfeat, const float4* __restrict__ bfeat) {
    const float4* feat = blockIdx.y ? bfeat : wfeat;
    unsigned* mask = blockIdx.y ? g_maskB : g_maskW;
    const int lane = threadIdx.x & 31;
    const int gw = (blockIdx.x * 256 + threadIdx.x) >> 5;          // global warp
    const int warpsTotal = (gridDim.x * 256) >> 5;                  // 65536
    const int nChunks = B_ROWS * N_IN / 128;                        // 786432 (= 12/warp)
    #pragma unroll 2
    for (int c = gw; c < nChunks; c += warpsTotal) {
        float4 v = __ldcs(&feat[c * 32 + lane]);
        unsigned bx = __ballot_sync(0xffffffffu, v.x != 0.f);
        unsigned by = __ballot_sync(0xffffffffu, v.y != 0.f);
        unsigned bz = __ballot_sync(0xffffffffu, v.z != 0.f);
        unsigned bw = __ballot_sync(0xffffffffu, v.w != 0.f);
        if (lane == 0)
            *reinterpret_cast<uint4*>(&mask[c * 4]) = make_uint4(bx, by, bz, bw);
    }
}

// ---------------------------------------------------------------------------
// Kernel 3: persistent NNUE forward. One thread per FT unit (256/CTA).
// Dynamic smem: l1_w cache (64 KB fp32).
// ---------------------------------------------------------------------------
extern __shared__ float s_l1w[];

__global__ void __launch_bounds__(256, 3)
nnue_main(const unsigned int* __restrict__ side,
          const float* __restrict__ ft_b,
          const float* __restrict__ l1_w,
          const float* __restrict__ l1_b,
          const float* __restrict__ l2_w,
          const float* __restrict__ l2_b,
          const float* __restrict__ l3_w,
          const float* __restrict__ l3_b,
          float* __restrict__ out)
{
    __shared__ float s_l2w[H2 * 33];
    __shared__ float s_o0[2 * H0];
    __shared__ float s_o1[H1];
    __shared__ int   s_idxW[CAP], s_idxB[CAP];
    __shared__ int   s_wsum[8];          // per-warp bit counts (warps 0-3: W, 4-7: B)

    const int tid  = threadIdx.x;
    const int warp = tid >> 5;
    const int lane = tid & 31;
    const int t    = tid & 127;          // position within half

    for (int i = tid; i < H1 * 2 * H0; i += 256) s_l1w[i] = l1_w[i];
    for (int i = tid; i < H2 * H1; i += 256)     s_l2w[(i >> 5) * 33 + (i & 31)] = l2_w[i];
    const float my_bias = ft_b[tid];
    __syncthreads();

    for (int row = blockIdx.x; row < B_ROWS; row += gridDim.x) {
        // ---- Phase 1: read mask row (3KB, L2), build deterministic index lists
        const unsigned* mrow =
            (tid < 128 ? g_maskW : g_maskB) + (size_t)row * MASK_WORDS;
        const unsigned m0 = mrow[t * 3 + 0];
        const unsigned m1 = mrow[t * 3 + 1];
        const unsigned m2 = mrow[t * 3 + 2];
        const int cnt = __popc(m0) + __popc(m1) + __popc(m2);

        // warp-inclusive scan of cnt
        int inc = cnt;
        #pragma unroll
        for (int d = 1; d < 32; d <<= 1) {
            int n = __shfl_up_sync(0xffffffffu, inc, d);
            if (lane >= d) inc += n;
        }
        if (lane == 31) s_wsum[warp] = inc;
        __syncthreads();

        const int hbase = (warp >> 2) * 4;     // 0 for W-half warps, 4 for B-half
        int base = 0;
        #pragma unroll
        for (int k2 = 0; k2 < 4; k2++)
            if (k2 < (warp & 3)) base += s_wsum[hbase + k2];
        int off = base + inc - cnt;

        int* list = (tid < 128) ? s_idxW : s_idxB;
        #pragma unroll
        for (int q = 0; q < 3; q++) {
            unsigned bits = (q == 0) ? m0 : (q == 1) ? m1 : m2;
            const int mm = t * 3 + q;
            const int jb = ((mm >> 2) << 7) + (mm & 3);   // chunk*128 + w
            while (bits) {
                int b = __ffs(bits) - 1;
                bits &= bits - 1;
                if (off < CAP) list[off] = (jb + (b << 2)) << 8;   // j * 256
                off++;
            }
        }
        const int nW = min(s_wsum[0] + s_wsum[1] + s_wsum[2] + s_wsum[3], CAP);
        const int nB = min(s_wsum[4] + s_wsum[5] + s_wsum[6] + s_wsum[7], CAP);
        __syncthreads();

        // ---- Phase 2: sparse FT gather from L2 (1KB coalesced per index), x4 MLP
        float aw0 = my_bias, aw1 = 0.f, aw2 = 0.f, aw3 = 0.f;
        float ab0 = my_bias, ab1 = 0.f, ab2 = 0.f, ab3 = 0.f;
        int k = 0;
        for (; k + 3 < nW; k += 4) {
            aw0 += __ldcs(&g_wT[s_idxW[k]     + tid]);
            aw1 += __ldcs(&g_wT[s_idxW[k + 1] + tid]);
            aw2 += __ldcs(&g_wT[s_idxW[k + 2] + tid]);
            aw3 += __ldcs(&g_wT[s_idxW[k + 3] + tid]);
        }
        for (; k < nW; k++) aw0 += __ldcs(&g_wT[s_idxW[k] + tid]);
        k = 0;
        for (; k + 3 < nB; k += 4) {
            ab0 += __ldcs(&g_wT[s_idxB[k]     + tid]);
            ab1 += __ldcs(&g_wT[s_idxB[k + 1] + tid]);
            ab2 += __ldcs(&g_wT[s_idxB[k + 2] + tid]);
            ab3 += __ldcs(&g_wT[s_idxB[k + 3] + tid]);
        }
        for (; k < nB; k++) ab0 += __ldcs(&g_wT[s_idxB[k] + tid]);

        const float o0w = fminf(fmaxf((aw0 + aw1) + (aw2 + aw3), 0.f), 1.f);
        const float o0b = fminf(fmaxf((ab0 + ab1) + (ab2 + ab3), 0.f), 1.f);

        const bool sd = (side[row] != 0u);    // int32 (1) or fp32 (0x3F800000) true
        s_o0[tid]      = sd ? o0w : o0b;
        s_o0[H0 + tid] = sd ? o0b : o0w;
        __syncthreads();

        // ---- Phase 3: o1 = clip(o0 @ l1_w.T + b); 8 warps x 4 outputs
        for (int kk = warp; kk < H1; kk += 8) {
            const float* wp = &s_l1w[kk * 2 * H0];
            float s = 0.f;
            #pragma unroll
            for (int i = lane; i < 2 * H0; i += 32) s += s_o0[i] * wp[i];
            #pragma unroll
            for (int o = 16; o; o >>= 1) s += __shfl_xor_sync(0xffffffffu, s, o);
            if (lane == 0) s_o1[kk] = fminf(fmaxf(s + l1_b[kk], 0.f), 1.f);
        }
        __syncthreads();

        // ---- Phase 4: l2 + l3 + sigmoid (warp 0; lane = l2 unit)
        if (warp == 0) {
            float s = l2_b[lane];
            #pragma unroll
            for (int i = 0; i < H1; i++) s += s_o1[i] * s_l2w[lane * 33 + i];
            const float o2 = fminf(fmaxf(s, 0.f), 1.f);
            float p = o2 * l3_w[lane];
            #pragma unroll
            for (int o = 16; o; o >>= 1) p += __shfl_xor_sync(0xffffffffu, p, o);
            if (lane == 0) {
                const float o3 = (p + l3_b[0]) * 1.5f;   // 300/200
                out[row] = 1.f / (1.f + expf(-o3));
            }
        }
        __syncthreads();   // protect smem before next row
    }
}

// ---------------------------------------------------------------------------
extern "C" void kernel_launch(void* const* d_in, const int* in_sizes, int n_in,
                              void* d_out, int out_size) {
    const float*        wfeat = (const float*)d_in[0];
    const float*        bfeat = (const float*)d_in[1];
    const unsigned int* side  = (const unsigned int*)d_in[2];
    const float*        ft_w  = (const float*)d_in[3];
    const float*        ft_b  = (const float*)d_in[4];
    const float*        l1_w  = (const float*)d_in[5];
    const float*        l1_b  = (const float*)d_in[6];
    const float*        l2_w  = (const float*)d_in[7];
    const float*        l2_b  = (const float*)d_in[8];
    const float*        l3_w  = (const float*)d_in[9];
    const float*        l3_b  = (const float*)d_in[10];
    float* out = (float*)d_out;

    // K1: transpose ft_w into g_wT (~6us)
    transpose_ftw<<<dim3(N_IN / 32, H0 / 32), dim3(32, 8)>>>(ft_w);

    // K2: streaming bitmask build (805MB read, should be DRAM-roofline)
    build_masks<<<dim3(8192, 2), 256>>>((const float4*)wfeat, (const float4*)bfeat);

    // K3: persistent main kernel (L2-fed)
    const int dyn_smem = H1 * 2 * H0 * (int)sizeof(float);   // 65536
    cudaFuncSetAttribute(nnue_main, cudaFuncAttributeMaxDynamicSharedMemorySize, dyn_smem);
    nnue_main<<<444, 256, dyn_smem>>>(
        side, ft_b, l1_w, l1_b, l2_w, l2_b, l3_w, l3_b, out);
}

// round 6
// speedup vs baseline: 1.9456x; 1.1228x over previous
#include <cuda_runtime.h>
#include <cuda_fp16.h>
#include <math.h>

#define B_ROWS 8192
#define N_IN   12288
#define H0     256
#define H1     32
#define H2     32
#define CAP    192          // ~31 expected actives/row; 192 is >25 sigma
#define MASK_WORDS 384      // 12288 bits / 32

// Transposed feature weights in fp16: wTh[j][h] = (half)ft_w[h][j]; 6.3 MB, L2-resident
__device__ __half g_wTh[N_IN * H0];
// Active-feature bitmasks: 3 KB per row per color, 25 MB total, L2-resident
__device__ unsigned g_maskW[B_ROWS * MASK_WORDS];
__device__ unsigned g_maskB[B_ROWS * MASK_WORDS];

// ---------------------------------------------------------------------------
// Kernel 1: tiled transpose ft_w (256 x 12288) fp32 -> g_wTh (12288 x 256) fp16
// ---------------------------------------------------------------------------
__global__ void transpose_ftw(const float* __restrict__ ft_w) {
    __shared__ float tile[32][33];
    int jBase = blockIdx.x * 32;
    int hBase = blockIdx.y * 32;
    int tx = threadIdx.x, ty = threadIdx.y;   // (32, 8)
    #pragma unroll
    for (int r = ty; r < 32; r += 8)
        tile[r][tx] = ft_w[(size_t)(hBase + r) * N_IN + (jBase + tx)];
    __syncthreads();
    #pragma unroll
    for (int r = ty; r < 32; r += 8)
        g_wTh[(size_t)(jBase + r) * H0 + (hBase + tx)] = __float2half_rn(tile[tx][r]);
}

// ---------------------------------------------------------------------------
// Kernel 2: streaming bitmask build. One warp-iteration = 128 consecutive
// floats (512B coalesced read) -> 4 ballot words (16B store by lane 0).
// Word layout: word (c*4+w), bit b  <=>  feature j = c*128 + 4*b + w.
// ---------------------------------------------------------------------------
__global__ void __launch_bounds__(256)
build_masks(const float4* __restrict__ wfeat, const float4* __restrict__ bfeat) {
    const float4* feat = blockIdx.y ? bfeat : wfeat;
    unsigned* mask = blockIdx.y ? g_maskB : g_maskW;
    const int lane = threadIdx.x & 31;
    const int gw = (blockIdx.x * 256 + threadIdx.x) >> 5;          // global warp
    const int warpsTotal = (gridDim.x * 256) >> 5;                  // 65536
    const int nChunks = B_ROWS * N_IN / 128;                        // 786432 (12/warp)
    #pragma unroll 4
    for (int c = gw; c < nChunks; c += warpsTotal) {
        float4 v = __ldcs(&feat[c * 32 + lane]);
        unsigned bx = __ballot_sync(0xffffffffu, v.x != 0.f);
        unsigned by = __ballot_sync(0xffffffffu, v.y != 0.f);
        unsigned bz = __ballot_sync(0xffffffffu, v.z != 0.f);
        unsigned bw = __ballot_sync(0xffffffffu, v.w != 0.f);
        if (lane == 0)
            *reinterpret_cast<uint4*>(&mask[c * 4]) = make_uint4(bx, by, bz, bw);
    }
}

// ---------------------------------------------------------------------------
// Kernel 3: persistent NNUE forward.
// Gather phase: thread t<128 accumulates WHITE units (2t, 2t+1) via half2;
// threads 128..255 accumulate BLACK. Both colors gather concurrently.
// Dynamic smem: l1_w cache (64 KB fp32).
// ---------------------------------------------------------------------------
extern __shared__ float s_l1w[];

__global__ void __launch_bounds__(256, 3)
nnue_main(const unsigned int* __restrict__ side,
          const float* __restrict__ ft_b,
          const float* __restrict__ l1_w,
          const float* __restrict__ l1_b,
          const float* __restrict__ l2_w,
          const float* __restrict__ l2_b,
          const float* __restrict__ l3_w,
          const float* __restrict__ l3_b,
          float* __restrict__ out)
{
    __shared__ float s_l2w[H2 * 33];
    __shared__ float s_o0[2 * H0];
    __shared__ float s_o1[H1];
    __shared__ int   s_idxW[CAP], s_idxB[CAP];
    __shared__ int   s_wsum[8];          // per-warp bit counts (warps 0-3: W, 4-7: B)

    const int tid  = threadIdx.x;
    const int warp = tid >> 5;
    const int lane = tid & 31;
    const int t    = tid & 127;          // position within color half
    const bool isW = (tid < 128);

    for (int i = tid; i < H1 * 2 * H0; i += 256) s_l1w[i] = l1_w[i];
    for (int i = tid; i < H2 * H1; i += 256)     s_l2w[(i >> 5) * 33 + (i & 31)] = l2_w[i];
    const float bias_x = ft_b[2 * t];
    const float bias_y = ft_b[2 * t + 1];
    const half2* __restrict__ wt2 = reinterpret_cast<const half2*>(g_wTh);
    __syncthreads();

    for (int row = blockIdx.x; row < B_ROWS; row += gridDim.x) {
        // ---- Phase 1: read mask row (3KB, L2), build deterministic index lists
        const unsigned* mrow = (isW ? g_maskW : g_maskB) + (size_t)row * MASK_WORDS;
        const unsigned m0 = mrow[t * 3 + 0];
        const unsigned m1 = mrow[t * 3 + 1];
        const unsigned m2 = mrow[t * 3 + 2];
        const int cnt = __popc(m0) + __popc(m1) + __popc(m2);

        // warp-inclusive scan of cnt
        int inc = cnt;
        #pragma unroll
        for (int d = 1; d < 32; d <<= 1) {
            int n = __shfl_up_sync(0xffffffffu, inc, d);
            if (lane >= d) inc += n;
        }
        if (lane == 31) s_wsum[warp] = inc;
        __syncthreads();

        const int hbase = (warp >> 2) * 4;
        int base = 0;
        #pragma unroll
        for (int k2 = 0; k2 < 4; k2++)
            if (k2 < (warp & 3)) base += s_wsum[hbase + k2];
        int off = base + inc - cnt;

        int* list = isW ? s_idxW : s_idxB;
        #pragma unroll
        for (int q = 0; q < 3; q++) {
            unsigned bits = (q == 0) ? m0 : (q == 1) ? m1 : m2;
            const int mm = t * 3 + q;
            const int jb = ((mm >> 2) << 7) + (mm & 3);   // chunk*128 + w
            while (bits) {
                int b = __ffs(bits) - 1;
                bits &= bits - 1;
                if (off < CAP) list[off] = (jb + (b << 2)) << 7;   // j * 128 (half2 row)
                off++;
            }
        }
        const int nW = min(s_wsum[0] + s_wsum[1] + s_wsum[2] + s_wsum[3], CAP);
        const int nB = min(s_wsum[4] + s_wsum[5] + s_wsum[6] + s_wsum[7], CAP);
        __syncthreads();

        // ---- Phase 2: sparse FT gather from L2 (512B coalesced half2 per index)
        const int nMine = isW ? nW : nB;
        float2 a0 = make_float2(bias_x, bias_y);
        float2 a1 = make_float2(0.f, 0.f);
        float2 a2 = make_float2(0.f, 0.f);
        float2 a3 = make_float2(0.f, 0.f);
        int k = 0;
        for (; k + 3 < nMine; k += 4) {
            float2 f0 = __half22float2(__ldcs(&wt2[list[k]     + t]));
            float2 f1 = __half22float2(__ldcs(&wt2[list[k + 1] + t]));
            float2 f2 = __half22float2(__ldcs(&wt2[list[k + 2] + t]));
            float2 f3 = __half22float2(__ldcs(&wt2[list[k + 3] + t]));
            a0.x += f0.x; a0.y += f0.y;
            a1.x += f1.x; a1.y += f1.y;
            a2.x += f2.x; a2.y += f2.y;
            a3.x += f3.x; a3.y += f3.y;
        }
        for (; k < nMine; k++) {
            float2 f = __half22float2(__ldcs(&wt2[list[k] + t]));
            a0.x += f.x; a0.y += f.y;
        }
        const float ox = fminf(fmaxf((a0.x + a1.x) + (a2.x + a3.x), 0.f), 1.f);
        const float oy = fminf(fmaxf((a0.y + a1.y) + (a2.y + a3.y), 0.f), 1.f);

        // Side-select concat: white goes first iff side; write directly into s_o0
        const bool sd = (side[row] != 0u);    // int32 (1) or fp32 (0x3F800000) true
        const int cbase = (isW == sd) ? 0 : H0;
        s_o0[cbase + 2 * t]     = ox;
        s_o0[cbase + 2 * t + 1] = oy;
        __syncthreads();

        // ---- Phase 3: o1 = clip(o0 @ l1_w.T + b); 8 warps x 4 outputs
        for (int kk = warp; kk < H1; kk += 8) {
            const float* wp = &s_l1w[kk * 2 * H0];
            float s = 0.f;
            #pragma unroll
            for (int i = lane; i < 2 * H0; i += 32) s += s_o0[i] * wp[i];
            #pragma unroll
            for (int o = 16; o; o >>= 1) s += __shfl_xor_sync(0xffffffffu, s, o);
            if (lane == 0) s_o1[kk] = fminf(fmaxf(s + l1_b[kk], 0.f), 1.f);
        }
        __syncthreads();

        // ---- Phase 4: l2 + l3 + sigmoid (warp 0; lane = l2 unit)
        if (warp == 0) {
            float s = l2_b[lane];
            #pragma unroll
            for (int i = 0; i < H1; i++) s += s_o1[i] * s_l2w[lane * 33 + i];
            const float o2 = fminf(fmaxf(s, 0.f), 1.f);
            float p = o2 * l3_w[lane];
            #pragma unroll
            for (int o = 16; o; o >>= 1) p += __shfl_xor_sync(0xffffffffu, p, o);
            if (lane == 0) {
                const float o3 = (p + l3_b[0]) * 1.5f;   // 300/200
                out[row] = 1.f / (1.f + expf(-o3));
            }
        }
        __syncthreads();   // protect smem before next row
    }
}

// ---------------------------------------------------------------------------
extern "C" void kernel_launch(void* const* d_in, const int* in_sizes, int n_in,
                              void* d_out, int out_size) {
    const float*        wfeat = (const float*)d_in[0];
    const float*        bfeat = (const float*)d_in[1];
    const unsigned int* side  = (const unsigned int*)d_in[2];
    const float*        ft_w  = (const float*)d_in[3];
    const float*        ft_b  = (const float*)d_in[4];
    const float*        l1_w  = (const float*)d_in[5];
    const float*        l1_b  = (const float*)d_in[6];
    const float*        l2_w  = (const float*)d_in[7];
    const float*        l2_b  = (const float*)d_in[8];
    const float*        l3_w  = (const float*)d_in[9];
    const float*        l3_b  = (const float*)d_in[10];
    float* out = (float*)d_out;

    // K1: transpose ft_w into g_wTh (fp16, ~8us)
    transpose_ftw<<<dim3(N_IN / 32, H0 / 32), dim3(32, 8)>>>(ft_w);

    // K2: streaming bitmask build (805MB read, DRAM-roofline)
    build_masks<<<dim3(8192, 2), 256>>>((const float4*)wfeat, (const float4*)bfeat);

    // K3: persistent main kernel (L2-fed)
    const int dyn_smem = H1 * 2 * H0 * (int)sizeof(float);   // 65536
    cudaFuncSetAttribute(nnue_main, cudaFuncAttributeMaxDynamicSharedMemorySize, dyn_smem);
    nnue_main<<<444, 256, dyn_smem>>>(
        side, ft_b, l1_w, l1_b, l2_w, l2_b, l3_w, l3_b, out);
}

// round 9
// speedup vs baseline: 2.3871x; 1.2269x over previous
#include <cuda_runtime.h>
#include <cuda_fp16.h>
#include <math.h>

#define B_ROWS 8192
#define N_IN   12288
#define H0     256
#define H1     32
#define H2     32
#define CAP    192        // ~31 expected actives/row; >25 sigma headroom
#define NWARPS 8

// Transposed fp16 feature weights: wTh[j][h]; 6.3 MB, L2-resident
__device__ __half g_wTh[N_IN * H0];
// Dynamic row dispatch counter
__device__ int g_rowCtr;

// ---------------------------------------------------------------------------
// Kernel 1: tiled transpose ft_w (256 x 12288) fp32 -> g_wTh (12288 x 256) fp16
// ---------------------------------------------------------------------------
__global__ void transpose_ftw(const float* __restrict__ ft_w) {
    __shared__ float tile[32][33];
    int jBase = blockIdx.x * 32;
    int hBase = blockIdx.y * 32;
    int tx = threadIdx.x, ty = threadIdx.y;   // (32, 8)
    #pragma unroll
    for (int r = ty; r < 32; r += 8)
        tile[r][tx] = ft_w[(size_t)(hBase + r) * N_IN + (jBase + tx)];
    __syncthreads();
    #pragma unroll
    for (int r = ty; r < 32; r += 8)
        g_wTh[(size_t)(jBase + r) * H0 + (hBase + tx)] = __float2half_rn(tile[tx][r]);
}

__global__ void init_ctr() { g_rowCtr = 0; }

// ---------------------------------------------------------------------------
// Kernel 2: fused warp-per-row NNUE. No CTA barriers in the row loop —
// warps run phase-independent so DRAM streaming and L2 gather overlap.
// Dynamic smem: l1_w transposed, stride-33 (512*33 fp32 = 66 KB).
// ---------------------------------------------------------------------------
extern __shared__ float s_l1wT[];   // [i*33 + kk], kk = l1 output unit

__device__ __forceinline__ float clip01(float x) {
    return fminf(fmaxf(x, 0.f), 1.f);
}

__global__ void __launch_bounds__(256, 2)
nnue_fused(const float4* __restrict__ wfeat,
           const float4* __restrict__ bfeat,
           const unsigned int* __restrict__ side,
           const float* __restrict__ ft_b,
           const float* __restrict__ l1_w,
           const float* __restrict__ l1_b,
           const float* __restrict__ l2_w,
           const float* __restrict__ l2_b,
           const float* __restrict__ l3_w,
           const float* __restrict__ l3_b,
           float* __restrict__ out)
{
    __shared__ float s_l2wT[H1 * 33];                 // [i*33 + n]
    __shared__ float s_o0[NWARPS][2 * H0];            // per-warp concat vector
    __shared__ unsigned short s_idx[NWARPS][2][CAP];  // per-warp W/B index lists

    const int tid  = threadIdx.x;
    const int warp = tid >> 5;
    const int lane = tid & 31;
    const unsigned lt = (1u << lane) - 1u;

    // One-time per CTA: transposed weight caches (stride-33, conflict-free)
    for (int e = tid; e < H1 * 2 * H0; e += 256)
        s_l1wT[(e & 511) * 33 + (e >> 9)] = l1_w[e];
    for (int e = tid; e < H2 * H1; e += 256)
        s_l2wT[(e & 31) * 33 + (e >> 5)] = l2_w[e];

    // Per-lane constants. Lane owns FT unit pairs (2*lane + 64q, +1), q=0..3.
    float bias[8];
    #pragma unroll
    for (int q = 0; q < 4; q++) {
        bias[2 * q]     = ft_b[2 * lane + 64 * q];
        bias[2 * q + 1] = ft_b[2 * lane + 64 * q + 1];
    }
    const float l1b  = l1_b[lane];
    const float l2b  = l2_b[lane];
    const float l3w  = l3_w[lane];
    const float l3b0 = l3_b[0];
    const half2* __restrict__ wt2 = reinterpret_cast<const half2*>(g_wTh);
    __syncthreads();

    unsigned short* listW = s_idx[warp][0];
    unsigned short* listB = s_idx[warp][1];
    float* o0 = s_o0[warp];

    // Stream one color row (96 KB total for both), ballot-compact active ids.
    auto scan = [&](const float4* __restrict__ rp, unsigned short* list) -> int {
        int n = 0;
        for (int ib = 0; ib < N_IN / 128; ib += 8) {   // 96 iters, batches of 8
            float4 v[8];
            #pragma unroll
            for (int u = 0; u < 8; u++) v[u] = __ldcs(&rp[(ib + u) * 32 + lane]);
            #pragma unroll
            for (int u = 0; u < 8; u++) {
                const int j0 = (ib + u) * 128 + 4 * lane;
                unsigned b;
                b = __ballot_sync(0xffffffffu, v[u].x != 0.f);
                if (v[u].x != 0.f) { int p = n + __popc(b & lt); if (p < CAP) list[p] = (unsigned short)j0; }
                n += __popc(b);
                b = __ballot_sync(0xffffffffu, v[u].y != 0.f);
                if (v[u].y != 0.f) { int p = n + __popc(b & lt); if (p < CAP) list[p] = (unsigned short)(j0 + 1); }
                n += __popc(b);
                b = __ballot_sync(0xffffffffu, v[u].z != 0.f);
                if (v[u].z != 0.f) { int p = n + __popc(b & lt); if (p < CAP) list[p] = (unsigned short)(j0 + 2); }
                n += __popc(b);
                b = __ballot_sync(0xffffffffu, v[u].w != 0.f);
                if (v[u].w != 0.f) { int p = n + __popc(b & lt); if (p < CAP) list[p] = (unsigned short)(j0 + 3); }
                n += __popc(b);
            }
        }
        return min(n, CAP);
    };

    // Gather: per index the warp pulls one 512B half2 row of wT from L2.
    auto gather = [&](const unsigned short* list, int n, float* acc) {
        int k = 0;
        for (; k + 1 < n; k += 2) {
            const int b0 = (int)list[k]     * (H0 / 2) + lane;
            const int b1 = (int)list[k + 1] * (H0 / 2) + lane;
            #pragma unroll
            for (int q = 0; q < 4; q++) {
                float2 f0 = __half22float2(wt2[b0 + 32 * q]);
                float2 f1 = __half22float2(wt2[b1 + 32 * q]);
                acc[2 * q]     += f0.x + f1.x;
                acc[2 * q + 1] += f0.y + f1.y;
            }
        }
        if (k < n) {
            const int b0 = (int)list[k] * (H0 / 2) + lane;
            #pragma unroll
            for (int q = 0; q < 4; q++) {
                float2 f0 = __half22float2(wt2[b0 + 32 * q]);
                acc[2 * q]     += f0.x;
                acc[2 * q + 1] += f0.y;
            }
        }
    };

    for (;;) {
        int row;
        if (lane == 0) row = atomicAdd(&g_rowCtr, 1);
        row = __shfl_sync(0xffffffffu, row, 0);
        if (row >= B_ROWS) break;

        // ---- Phase A: stream features (DRAM), build lists
        const int nW = scan(wfeat + (size_t)row * (N_IN / 4), listW);
        const int nB = scan(bfeat + (size_t)row * (N_IN / 4), listB);
        __syncwarp();

        // ---- Phase B: sparse FT gather (L2)
        float aw[8], ab[8];
        #pragma unroll
        for (int i = 0; i < 8; i++) { aw[i] = bias[i]; ab[i] = bias[i]; }
        gather(listW, nW, aw);
        gather(listB, nB, ab);

        // ---- Phase C: clip + side-ordered concat into this warp's o0
        const bool sd = (side[row] != 0u);   // int32 (1) or fp32 (0x3F800000) true
        const int bw = sd ? 0 : H0;
        const int bb = sd ? H0 : 0;
        #pragma unroll
        for (int q = 0; q < 4; q++) {
            const int u = 2 * lane + 64 * q;
            o0[bw + u]     = clip01(aw[2 * q]);
            o0[bw + u + 1] = clip01(aw[2 * q + 1]);
            o0[bb + u]     = clip01(ab[2 * q]);
            o0[bb + u + 1] = clip01(ab[2 * q + 1]);
        }
        __syncwarp();

        // ---- Phase D: l1 (lane = output unit; broadcast o0, conflict-free w)
        float s = l1b;
        const float4* o04 = reinterpret_cast<const float4*>(o0);
        #pragma unroll 4
        for (int i4 = 0; i4 < (2 * H0) / 4; i4++) {
            const float4 ov = o04[i4];
            const int i = i4 * 4;
            s += ov.x * s_l1wT[i * 33 + lane]
               + ov.y * s_l1wT[(i + 1) * 33 + lane]
               + ov.z * s_l1wT[(i + 2) * 33 + lane]
               + ov.w * s_l1wT[(i + 3) * 33 + lane];
        }
        const float o1 = clip01(s);

        // ---- Phase E: l2 via shfl broadcast, then l3 + sigmoid
        float s2 = l2b;
        #pragma unroll
        for (int i = 0; i < H1; i++)
            s2 += __shfl_sync(0xffffffffu, o1, i) * s_l2wT[i * 33 + lane];
        const float o2 = clip01(s2);

        float p = o2 * l3w;
        #pragma unroll
        for (int o = 16; o; o >>= 1) p += __shfl_xor_sync(0xffffffffu, p, o);
        if (lane == 0)
            out[row] = 1.f / (1.f + expf(-1.5f * (p + l3b0)));   // 300/200 = 1.5

        __syncwarp();   // o0/lists reuse safety before next row
    }
}

// ---------------------------------------------------------------------------
extern "C" void kernel_launch(void* const* d_in, const int* in_sizes, int n_in,
                              void* d_out, int out_size) {
    const float*        wfeat = (const float*)d_in[0];
    const float*        bfeat = (const float*)d_in[1];
    const unsigned int* side  = (const unsigned int*)d_in[2];
    const float*        ft_w  = (const float*)d_in[3];
    const float*        ft_b  = (const float*)d_in[4];
    const float*        l1_w  = (const float*)d_in[5];
    const float*        l1_b  = (const float*)d_in[6];
    const float*        l2_w  = (const float*)d_in[7];
    const float*        l2_b  = (const float*)d_in[8];
    const float*        l3_w  = (const float*)d_in[9];
    const float*        l3_b  = (const float*)d_in[10];
    float* out = (float*)d_out;

    // K1: transpose ft_w into fp16 g_wTh (~10us)
    transpose_ftw<<<dim3(N_IN / 32, H0 / 32), dim3(32, 8)>>>(ft_w);

    // K2: reset row dispatcher
    init_ctr<<<1, 1>>>();

    // K3: fused warp-per-row kernel; 66KB dynamic smem for transposed l1_w
    const int dyn_smem = 2 * H0 * 33 * (int)sizeof(float);   // 67584
    cudaFuncSetAttribute(nnue_fused, cudaFuncAttributeMaxDynamicSharedMemorySize, dyn_smem);
    nnue_fused<<<296, 256, dyn_smem>>>(
        (const float4*)wfeat, (const float4*)bfeat, side,
        ft_b, l1_w, l1_b, l2_w, l2_b, l3_w, l3_b, out);
}

// round 11
// speedup vs baseline: 2.5450x; 1.0661x over previous
#include <cuda_runtime.h>
#include <cuda_fp16.h>
#include <math.h>

#define B_ROWS 8192
#define N_IN   12288
#define H0     256
#define H1     32
#define H2     32
#define CAP    192        // ~31 expected actives/row; >25 sigma headroom
#define NWARPS 8

// Transposed fp16 feature weights: wTh[j][h]; 6.3 MB, L2-resident
__device__ __half g_wTh[N_IN * H0];
// Dynamic row dispatch counter
__device__ int g_rowCtr;

// ---------------------------------------------------------------------------
// Kernel 1: tiled transpose ft_w (256 x 12288) fp32 -> g_wTh (12288 x 256) fp16
// ---------------------------------------------------------------------------
__global__ void transpose_ftw(const float* __restrict__ ft_w) {
    __shared__ float tile[32][33];
    int jBase = blockIdx.x * 32;
    int hBase = blockIdx.y * 32;
    int tx = threadIdx.x, ty = threadIdx.y;   // (32, 8)
    #pragma unroll
    for (int r = ty; r < 32; r += 8)
        tile[r][tx] = ft_w[(size_t)(hBase + r) * N_IN + (jBase + tx)];
    __syncthreads();
    #pragma unroll
    for (int r = ty; r < 32; r += 8)
        g_wTh[(size_t)(jBase + r) * H0 + (hBase + tx)] = __float2half_rn(tile[tx][r]);
}

__global__ void init_ctr() { g_rowCtr = 0; }

// ---------------------------------------------------------------------------
// Kernel 2: fused warp-per-row NNUE. No CTA barriers in the row loop.
// Dynamic smem: l1_w as half2 pairs, transposed, stride-33 (33.8 KB).
// 3 CTAs/SM -> 24 warps/SM.
// ---------------------------------------------------------------------------
extern __shared__ __half2 s_l1h2[];   // [p*33 + kk]: (w[kk][2p], w[kk][2p+1])

__device__ __forceinline__ float clip01(float x) {
    return fminf(fmaxf(x, 0.f), 1.f);
}

__global__ void __launch_bounds__(256, 3)
nnue_fused(const float4* __restrict__ wfeat,
           const float4* __restrict__ bfeat,
           const unsigned int* __restrict__ side,
           const float* __restrict__ ft_b,
           const float* __restrict__ l1_w,
           const float* __restrict__ l1_b,
           const float* __restrict__ l2_w,
           const float* __restrict__ l2_b,
           const float* __restrict__ l3_w,
           const float* __restrict__ l3_b,
           float* __restrict__ out)
{
    __shared__ float s_l2wT[H1 * 33];                 // [i*33 + n]
    __shared__ float s_o0[NWARPS][2 * H0];            // per-warp concat vector
    __shared__ unsigned short s_idx[NWARPS][2][CAP];  // per-warp W/B index lists

    const int tid  = threadIdx.x;
    const int warp = tid >> 5;
    const int lane = tid & 31;
    const unsigned lt = (1u << lane) - 1u;

    // One-time: l1_w fp32 -> half2-paired transposed cache (conflict-free)
    for (int idx = tid; idx < (H0) * H1; idx += 256) {    // 256 pairs x 32 outs
        const int p = idx >> 5, kk = idx & 31;
        s_l1h2[p * 33 + kk] =
            __floats2half2_rn(l1_w[kk * 2 * H0 + 2 * p], l1_w[kk * 2 * H0 + 2 * p + 1]);
    }
    for (int e = tid; e < H2 * H1; e += 256)
        s_l2wT[(e & 31) * 33 + (e >> 5)] = l2_w[e];

    // Per-lane constants. Lane owns FT unit pairs (2*lane + 64q, +1), q=0..3.
    float bias[8];
    #pragma unroll
    for (int q = 0; q < 4; q++) {
        bias[2 * q]     = ft_b[2 * lane + 64 * q];
        bias[2 * q + 1] = ft_b[2 * lane + 64 * q + 1];
    }
    const float l1b  = l1_b[lane];
    const float l2b  = l2_b[lane];
    const float l3w  = l3_w[lane];
    const float l3b0 = l3_b[0];
    const half2* __restrict__ wt2 = reinterpret_cast<const half2*>(g_wTh);
    __syncthreads();

    unsigned short* listW = s_idx[warp][0];
    unsigned short* listB = s_idx[warp][1];
    float* o0 = s_o0[warp];

    // Stream one color row (48 KB), ballot-compact active ids.
    // Fast path: ~73% of 128-feature chunks have zero actives -> 1 ballot only.
    auto scan = [&](const float4* __restrict__ rp, unsigned short* list) -> int {
        int n = 0;
        for (int ib = 0; ib < N_IN / 128; ib += 8) {   // 96 iters, batches of 8
            float4 v[8];
            #pragma unroll
            for (int u = 0; u < 8; u++) v[u] = __ldcs(&rp[(ib + u) * 32 + lane]);
            #pragma unroll
            for (int u = 0; u < 8; u++) {
                const bool nz = (v[u].x != 0.f) | (v[u].y != 0.f) |
                                (v[u].z != 0.f) | (v[u].w != 0.f);
                if (__ballot_sync(0xffffffffu, nz) == 0u) continue;  // uniform
                const int j0 = (ib + u) * 128 + 4 * lane;
                unsigned b;
                b = __ballot_sync(0xffffffffu, v[u].x != 0.f);
                if (v[u].x != 0.f) { int p = n + __popc(b & lt); if (p < CAP) list[p] = (unsigned short)j0; }
                n += __popc(b);
                b = __ballot_sync(0xffffffffu, v[u].y != 0.f);
                if (v[u].y != 0.f) { int p = n + __popc(b & lt); if (p < CAP) list[p] = (unsigned short)(j0 + 1); }
                n += __popc(b);
                b = __ballot_sync(0xffffffffu, v[u].z != 0.f);
                if (v[u].z != 0.f) { int p = n + __popc(b & lt); if (p < CAP) list[p] = (unsigned short)(j0 + 2); }
                n += __popc(b);
                b = __ballot_sync(0xffffffffu, v[u].w != 0.f);
                if (v[u].w != 0.f) { int p = n + __popc(b & lt); if (p < CAP) list[p] = (unsigned short)(j0 + 3); }
                n += __popc(b);
            }
        }
        return min(n, CAP);
    };

    // Gather: 4 indices x 4 half2 loads in flight (16 L2 loads / warp-iter).
    auto gather = [&](const unsigned short* list, int n, float* acc) {
        int k = 0;
        for (; k + 3 < n; k += 4) {
            const int b0 = (int)list[k]     * (H0 / 2) + lane;
            const int b1 = (int)list[k + 1] * (H0 / 2) + lane;
            const int b2 = (int)list[k + 2] * (H0 / 2) + lane;
            const int b3 = (int)list[k + 3] * (H0 / 2) + lane;
            #pragma unroll
            for (int q = 0; q < 4; q++) {
                float2 f0 = __half22float2(wt2[b0 + 32 * q]);
                float2 f1 = __half22float2(wt2[b1 + 32 * q]);
                float2 f2 = __half22float2(wt2[b2 + 32 * q]);
                float2 f3 = __half22float2(wt2[b3 + 32 * q]);
                acc[2 * q]     += (f0.x + f1.x) + (f2.x + f3.x);
                acc[2 * q + 1] += (f0.y + f1.y) + (f2.y + f3.y);
            }
        }
        for (; k < n; k++) {
            const int b0 = (int)list[k] * (H0 / 2) + lane;
            #pragma unroll
            for (int q = 0; q < 4; q++) {
                float2 f0 = __half22float2(wt2[b0 + 32 * q]);
                acc[2 * q]     += f0.x;
                acc[2 * q + 1] += f0.y;
            }
        }
    };

    for (;;) {
        int row;
        if (lane == 0) row = atomicAdd(&g_rowCtr, 1);
        row = __shfl_sync(0xffffffffu, row, 0);
        if (row >= B_ROWS) break;

        // ---- Phase A: stream features (DRAM), build lists
        const int nW = scan(wfeat + (size_t)row * (N_IN / 4), listW);
        const int nB = scan(bfeat + (size_t)row * (N_IN / 4), listB);
        __syncwarp();

        // ---- Phase B: sparse FT gather (L2)
        float aw[8], ab[8];
        #pragma unroll
        for (int i = 0; i < 8; i++) { aw[i] = bias[i]; ab[i] = bias[i]; }
        gather(listW, nW, aw);
        gather(listB, nB, ab);

        // ---- Phase C: clip + side-ordered concat into this warp's o0
        const bool sd = (side[row] != 0u);   // int32 (1) or fp32 (0x3F800000) true
        const int bw = sd ? 0 : H0;
        const int bb = sd ? H0 : 0;
        #pragma unroll
        for (int q = 0; q < 4; q++) {
            const int u = 2 * lane + 64 * q;
            o0[bw + u]     = clip01(aw[2 * q]);
            o0[bw + u + 1] = clip01(aw[2 * q + 1]);
            o0[bb + u]     = clip01(ab[2 * q]);
            o0[bb + u + 1] = clip01(ab[2 * q + 1]);
        }
        __syncwarp();

        // ---- Phase D: l1 (lane = output unit; fp16 weights, fp32 accum)
        float s = l1b;
        const float4* o04 = reinterpret_cast<const float4*>(o0);
        #pragma unroll 8
        for (int pp = 0; pp < (2 * H0) / 4; pp++) {   // float4 = pairs 2pp, 2pp+1
            const float4 ov = o04[pp];
            const float2 w0 = __half22float2(s_l1h2[(2 * pp)     * 33 + lane]);
            const float2 w1 = __half22float2(s_l1h2[(2 * pp + 1) * 33 + lane]);
            s += ov.x * w0.x + ov.y * w0.y + ov.z * w1.x + ov.w * w1.y;
        }
        const float o1 = clip01(s);

        // ---- Phase E: l2 via shfl broadcast, then l3 + sigmoid
        float s2 = l2b;
        #pragma unroll
        for (int i = 0; i < H1; i++)
            s2 += __shfl_sync(0xffffffffu, o1, i) * s_l2wT[i * 33 + lane];
        const float o2 = clip01(s2);

        float p = o2 * l3w;
        #pragma unroll
        for (int o = 16; o; o >>= 1) p += __shfl_xor_sync(0xffffffffu, p, o);
        if (lane == 0)
            out[row] = 1.f / (1.f + expf(-1.5f * (p + l3b0)));   // 300/200 = 1.5

        __syncwarp();   // o0/lists reuse safety before next row
    }
}

// ---------------------------------------------------------------------------
extern "C" void kernel_launch(void* const* d_in, const int* in_sizes, int n_in,
                              void* d_out, int out_size) {
    const float*        wfeat = (const float*)d_in[0];
    const float*        bfeat = (const float*)d_in[1];
    const unsigned int* side  = (const unsigned int*)d_in[2];
    const float*        ft_w  = (const float*)d_in[3];
    const float*        ft_b  = (const float*)d_in[4];
    const float*        l1_w  = (const float*)d_in[5];
    const float*        l1_b  = (const float*)d_in[6];
    const float*        l2_w  = (const float*)d_in[7];
    const float*        l2_b  = (const float*)d_in[8];
    const float*        l3_w  = (const float*)d_in[9];
    const float*        l3_b  = (const float*)d_in[10];
    float* out = (float*)d_out;

    // K1: transpose ft_w into fp16 g_wTh (~10us)
    transpose_ftw<<<dim3(N_IN / 32, H0 / 32), dim3(32, 8)>>>(ft_w);

    // K2: reset row dispatcher
    init_ctr<<<1, 1>>>();

    // K3: fused warp-per-row kernel; 33.8KB dynamic smem (half2 l1_w), 3 CTAs/SM
    const int dyn_smem = H0 * 33 * (int)sizeof(__half2);   // 33792
    cudaFuncSetAttribute(nnue_fused, cudaFuncAttributeMaxDynamicSharedMemorySize, dyn_smem);
    nnue_fused<<<444, 256, dyn_smem>>>(
        (const float4*)wfeat, (const float4*)bfeat, side,
        ft_b, l1_w, l1_b, l2_w, l2_b, l3_w, l3_b, out);
}

// round 12
// speedup vs baseline: 2.7149x; 1.0668x over previous
#include <cuda_runtime.h>
#include <cuda_fp16.h>
#include <math.h>

#define B_ROWS 8192
#define N_IN   12288
#define H0     256
#define H1     32
#define H2     32
#define CAP    192        // ~31 expected actives/color-row; >25 sigma headroom
#define NWARPS 8

// Transposed fp16 feature weights: wTh[j][h]; 6.3 MB, L2-resident
__device__ __half g_wTh[N_IN * H0];
// Per-(row,color) clipped FT halves: 16.8 MB staging (L2)
__device__ float g_half[B_ROWS * 2 * H0];
// Row completion counters + dispatch counter
__device__ unsigned g_done[B_ROWS];
__device__ int g_rowCtr;

// ---------------------------------------------------------------------------
// Kernel 1: tiled transpose ft_w (256 x 12288) fp32 -> g_wTh (12288 x 256) fp16
// ---------------------------------------------------------------------------
__global__ void transpose_ftw(const float* __restrict__ ft_w) {
    __shared__ float tile[32][33];
    int jBase = blockIdx.x * 32;
    int hBase = blockIdx.y * 32;
    int tx = threadIdx.x, ty = threadIdx.y;   // (32, 8)
    #pragma unroll
    for (int r = ty; r < 32; r += 8)
        tile[r][tx] = ft_w[(size_t)(hBase + r) * N_IN + (jBase + tx)];
    __syncthreads();
    #pragma unroll
    for (int r = ty; r < 32; r += 8)
        g_wTh[(size_t)(jBase + r) * H0 + (hBase + tx)] = __float2half_rn(tile[tx][r]);
}

__global__ void init_state() {
    const int i = blockIdx.x * blockDim.x + threadIdx.x;
    if (i < B_ROWS) g_done[i] = 0u;
    if (i == 0) g_rowCtr = 0;
}

// ---------------------------------------------------------------------------
// Kernel 2: fused NNUE, work unit = (row, color). 16384 units -> better
// end-of-kernel balance than warp-per-row. Finisher (2nd unit of a row)
// assembles both halves and runs the MLP.
// ---------------------------------------------------------------------------
extern __shared__ __half2 s_l1h2[];   // [p*33 + kk]: (w[kk][2p], w[kk][2p+1])

__device__ __forceinline__ float clip01(float x) {
    return fminf(fmaxf(x, 0.f), 1.f);
}

__global__ void __launch_bounds__(256, 3)
nnue_fused(const float4* __restrict__ wfeat,
           const float4* __restrict__ bfeat,
           const unsigned int* __restrict__ side,
           const float* __restrict__ ft_b,
           const float* __restrict__ l1_w,
           const float* __restrict__ l1_b,
           const float* __restrict__ l2_w,
           const float* __restrict__ l2_b,
           const float* __restrict__ l3_w,
           const float* __restrict__ l3_b,
           float* __restrict__ out)
{
    __shared__ float s_l2wT[H1 * 33];                 // [i*33 + n]
    __shared__ float s_o0[NWARPS][2 * H0];            // per-warp concat vector
    __shared__ unsigned short s_idx[NWARPS][CAP];     // per-warp index list

    const int tid  = threadIdx.x;
    const int warp = tid >> 5;
    const int lane = tid & 31;
    const unsigned lt = (1u << lane) - 1u;

    // One-time: l1_w fp32 -> half2-paired transposed cache (conflict-free)
    for (int idx = tid; idx < H0 * H1; idx += 256) {
        const int p = idx >> 5, kk = idx & 31;
        s_l1h2[p * 33 + kk] =
            __floats2half2_rn(l1_w[kk * 2 * H0 + 2 * p], l1_w[kk * 2 * H0 + 2 * p + 1]);
    }
    for (int e = tid; e < H2 * H1; e += 256)
        s_l2wT[(e & 31) * 33 + (e >> 5)] = l2_w[e];

    // Per-lane constants. Lane owns FT unit pairs (2*lane + 64q, +1), q=0..3.
    float bias[8];
    #pragma unroll
    for (int q = 0; q < 4; q++) {
        bias[2 * q]     = ft_b[2 * lane + 64 * q];
        bias[2 * q + 1] = ft_b[2 * lane + 64 * q + 1];
    }
    const float l1b  = l1_b[lane];
    const float l2b  = l2_b[lane];
    const float l3w  = l3_w[lane];
    const float l3b0 = l3_b[0];
    const half2* __restrict__ wt2 = reinterpret_cast<const half2*>(g_wTh);
    __syncthreads();

    unsigned short* list = s_idx[warp];
    float* o0 = s_o0[warp];

    // Stream one color row (48 KB), ballot-compact active ids.
    // Fast path: ~73% of 128-feature chunks are empty -> 1 ballot only.
    auto scan = [&](const float4* __restrict__ rp) -> int {
        int n = 0;
        for (int ib = 0; ib < N_IN / 128; ib += 8) {   // 96 iters, batches of 8
            float4 v[8];
            #pragma unroll
            for (int u = 0; u < 8; u++) v[u] = __ldcs(&rp[(ib + u) * 32 + lane]);
            #pragma unroll
            for (int u = 0; u < 8; u++) {
                const bool nz = (v[u].x != 0.f) | (v[u].y != 0.f) |
                                (v[u].z != 0.f) | (v[u].w != 0.f);
                if (__ballot_sync(0xffffffffu, nz) == 0u) continue;  // uniform
                const int j0 = (ib + u) * 128 + 4 * lane;
                unsigned b;
                b = __ballot_sync(0xffffffffu, v[u].x != 0.f);
                if (v[u].x != 0.f) { int p = n + __popc(b & lt); if (p < CAP) list[p] = (unsigned short)j0; }
                n += __popc(b);
                b = __ballot_sync(0xffffffffu, v[u].y != 0.f);
                if (v[u].y != 0.f) { int p = n + __popc(b & lt); if (p < CAP) list[p] = (unsigned short)(j0 + 1); }
                n += __popc(b);
                b = __ballot_sync(0xffffffffu, v[u].z != 0.f);
                if (v[u].z != 0.f) { int p = n + __popc(b & lt); if (p < CAP) list[p] = (unsigned short)(j0 + 2); }
                n += __popc(b);
                b = __ballot_sync(0xffffffffu, v[u].w != 0.f);
                if (v[u].w != 0.f) { int p = n + __popc(b & lt); if (p < CAP) list[p] = (unsigned short)(j0 + 3); }
                n += __popc(b);
            }
        }
        return min(n, CAP);
    };

    // Gather: 4 indices x 4 half2 loads in flight (16 L2 loads / warp-iter).
    auto gather = [&](int n, float* acc) {
        int k = 0;
        for (; k + 3 < n; k += 4) {
            const int b0 = (int)list[k]     * (H0 / 2) + lane;
            const int b1 = (int)list[k + 1] * (H0 / 2) + lane;
            const int b2 = (int)list[k + 2] * (H0 / 2) + lane;
            const int b3 = (int)list[k + 3] * (H0 / 2) + lane;
            #pragma unroll
            for (int q = 0; q < 4; q++) {
                float2 f0 = __half22float2(wt2[b0 + 32 * q]);
                float2 f1 = __half22float2(wt2[b1 + 32 * q]);
                float2 f2 = __half22float2(wt2[b2 + 32 * q]);
                float2 f3 = __half22float2(wt2[b3 + 32 * q]);
                acc[2 * q]     += (f0.x + f1.x) + (f2.x + f3.x);
                acc[2 * q + 1] += (f0.y + f1.y) + (f2.y + f3.y);
            }
        }
        for (; k < n; k++) {
            const int b0 = (int)list[k] * (H0 / 2) + lane;
            #pragma unroll
            for (int q = 0; q < 4; q++) {
                float2 f0 = __half22float2(wt2[b0 + 32 * q]);
                acc[2 * q]     += f0.x;
                acc[2 * q + 1] += f0.y;
            }
        }
    };

    for (;;) {
        int u;
        if (lane == 0) u = atomicAdd(&g_rowCtr, 1);
        u = __shfl_sync(0xffffffffu, u, 0);
        if (u >= 2 * B_ROWS) break;
        const int row = u >> 1;
        const int col = u & 1;           // 0 = white, 1 = black

        // ---- Phase A: stream this color's features (DRAM), build list
        const int n = scan((col ? bfeat : wfeat) + (size_t)row * (N_IN / 4));
        __syncwarp();

        // ---- Phase B: sparse FT gather (L2) + clip
        float acc[8];
        #pragma unroll
        for (int i = 0; i < 8; i++) acc[i] = bias[i];
        gather(n, acc);
        #pragma unroll
        for (int i = 0; i < 8; i++) acc[i] = clip01(acc[i]);

        // ---- Phase C: publish this half; second arrival finishes the row
        float* hb = &g_half[(size_t)u * H0];
        #pragma unroll
        for (int q = 0; q < 4; q++) {
            float2 p2 = make_float2(acc[2 * q], acc[2 * q + 1]);
            __stcs(reinterpret_cast<float2*>(hb + 64 * q + 2 * lane), p2);
        }
        __threadfence();
        unsigned old;
        if (lane == 0) old = atomicAdd(&g_done[row], 1u);
        old = __shfl_sync(0xffffffffu, old, 0);
        if (old == 0u) continue;        // first half done; other warp finishes
        __threadfence();                // acquire: other half's stores visible

        // ---- Phase D0: assemble concat (own half = regs, other = L2)
        const bool sd = (side[row] != 0u);   // int32 (1) or fp32 (0x3F800000) true
        // white first iff sd; own color is `col`
        const int baseOwn   = ((col == 0) == sd) ? 0 : H0;
        const int baseOther = H0 - baseOwn;
        const float* ho = &g_half[(size_t)(row * 2 + (1 - col)) * H0];
        #pragma unroll
        for (int q = 0; q < 4; q++) {
            const int h = 64 * q + 2 * lane;
            o0[baseOwn + h]     = acc[2 * q];
            o0[baseOwn + h + 1] = acc[2 * q + 1];
            const float2 p2 = __ldcg(reinterpret_cast<const float2*>(ho + h));
            o0[baseOther + h]     = p2.x;
            o0[baseOther + h + 1] = p2.y;
        }
        __syncwarp();

        // ---- Phase D: l1 (lane = output unit; fp16 weights, fp32 accum)
        float s = l1b;
        const float4* o04 = reinterpret_cast<const float4*>(o0);
        #pragma unroll 8
        for (int pp = 0; pp < (2 * H0) / 4; pp++) {
            const float4 ov = o04[pp];
            const float2 w0 = __half22float2(s_l1h2[(2 * pp)     * 33 + lane]);
            const float2 w1 = __half22float2(s_l1h2[(2 * pp + 1) * 33 + lane]);
            s += ov.x * w0.x + ov.y * w0.y + ov.z * w1.x + ov.w * w1.y;
        }
        const float o1 = clip01(s);

        // ---- Phase E: l2 via shfl broadcast, then l3 + sigmoid
        float s2 = l2b;
        #pragma unroll
        for (int i = 0; i < H1; i++)
            s2 += __shfl_sync(0xffffffffu, o1, i) * s_l2wT[i * 33 + lane];
        const float o2 = clip01(s2);

        float p = o2 * l3w;
        #pragma unroll
        for (int o = 16; o; o >>= 1) p += __shfl_xor_sync(0xffffffffu, p, o);
        if (lane == 0)
            out[row] = 1.f / (1.f + expf(-1.5f * (p + l3b0)));   // 300/200 = 1.5

        __syncwarp();   // o0/list reuse safety before next unit
    }
}

// ---------------------------------------------------------------------------
extern "C" void kernel_launch(void* const* d_in, const int* in_sizes, int n_in,
                              void* d_out, int out_size) {
    const float*        wfeat = (const float*)d_in[0];
    const float*        bfeat = (const float*)d_in[1];
    const unsigned int* side  = (const unsigned int*)d_in[2];
    const float*        ft_w  = (const float*)d_in[3];
    const float*        ft_b  = (const float*)d_in[4];
    const float*        l1_w  = (const float*)d_in[5];
    const float*        l1_b  = (const float*)d_in[6];
    const float*        l2_w  = (const float*)d_in[7];
    const float*        l2_b  = (const float*)d_in[8];
    const float*        l3_w  = (const float*)d_in[9];
    const float*        l3_b  = (const float*)d_in[10];
    float* out = (float*)d_out;

    // K1: transpose ft_w into fp16 g_wTh (~10us)
    transpose_ftw<<<dim3(N_IN / 32, H0 / 32), dim3(32, 8)>>>(ft_w);

    // K2: reset dispatch + done counters
    init_state<<<(B_ROWS + 255) / 256, 256>>>();

    // K3: fused (row,color)-unit kernel; 33.8KB dynamic smem, 3 CTAs/SM
    const int dyn_smem = H0 * 33 * (int)sizeof(__half2);   // 33792
    cudaFuncSetAttribute(nnue_fused, cudaFuncAttributeMaxDynamicSharedMemorySize, dyn_smem);
    nnue_fused<<<444, 256, dyn_smem>>>(
        (const float4*)wfeat, (const float4*)bfeat, side,
        ft_b, l1_w, l1_b, l2_w, l2_b, l3_w, l3_b, out);
}